// round 17
// baseline (speedup 1.0000x reference)
#include <cuda_runtime.h>
#include <cuda_fp16.h>
#include <math.h>
#include <stdint.h>

#define NB 8
#define NT 1024
#define NC 1024
#define NH 16
#define NM (NB*NT)
#define KH 512            // K/2 (fp16 pairs packed along K)
#define NSEG 8
#define TSEG (NT/NSEG)

// ---------------- scratch (static device globals, no allocation) -------------
__device__ uint32_t g_k16 [NM*KH];        // exp(clip(k)) packed half2
__device__ uint32_t g_v16 [NM*KH];        // v packed half2
__device__ uint32_t g_r16 [NM*KH];        // r packed half2
__device__ float    g_sumk[NM*NC];        // per-segment local cumsum (f32)
__device__ float    g_segtot[NB*NSEG*NC];
__device__ uint32_t g_Ah  [NM*KH];        // packed f16x2 of current A operand
__device__ uint32_t g_Wh  [4*NC*KH];      // Wk,Wv,Wr,Wo rounded to fp16 (B operand)
__device__ uint32_t g_WWh [NH*NT*KH];     // decay matrix W[h][t][u] fp16 (A of wkv)
__device__ uint32_t g_kvTh[NB*NH*64*KH];  // kv^T [bh][c][u-pairs] rounded fp16

// ---------------- helpers -----------------------------------------------------
__device__ __forceinline__ uint32_t pack2h(float a, float b) {
    __half ha = __float2half_rn(a), hb = __float2half_rn(b);
    return (uint32_t)__half_as_ushort(ha) | ((uint32_t)__half_as_ushort(hb) << 16);
}

__device__ __forceinline__ float2 unpack2h(uint32_t p) {
    __half2 h = *(__half2*)&p;
    return make_float2(__half2float(__low2half(h)), __half2float(__high2half(h)));
}

__device__ __forceinline__ void mma_f16(float* c, const uint32_t* a,
                                        uint32_t b0, uint32_t b1) {
    asm volatile(
        "mma.sync.aligned.m16n8k16.row.col.f32.f16.f16.f32 "
        "{%0,%1,%2,%3},{%4,%5,%6,%7},{%8,%9},{%0,%1,%2,%3};"
        : "+f"(c[0]), "+f"(c[1]), "+f"(c[2]), "+f"(c[3])
        : "r"(a[0]), "r"(a[1]), "r"(a[2]), "r"(a[3]), "r"(b0), "r"(b1));
}

__device__ __forceinline__ void ldm_x4(uint32_t* r, uint32_t addr) {
    asm volatile("ldmatrix.sync.aligned.m8n8.x4.shared.b16 {%0,%1,%2,%3}, [%4];"
                 : "=r"(r[0]), "=r"(r[1]), "=r"(r[2]), "=r"(r[3]) : "r"(addr));
}

__device__ __forceinline__ void cpa16(uint32_t d, const void* s) {
    asm volatile("cp.async.cg.shared.global [%0], [%1], 16;" :: "r"(d), "l"(s));
}
#define CP_COMMIT() asm volatile("cp.async.commit_group;")
#define CP_WAIT1()  asm volatile("cp.async.wait_group 1;")
#define CP_WAIT0()  asm volatile("cp.async.wait_group 0;")

// ---------------- fused prep: weights round + decay matrix + time-shift -------
#define PREP_B0 (4*NC*KH/256)
#define PREP_B1 (NH*NT*KH/256)
#define PREP_B2 (NM*KH/256)

__global__ void prep_kernel(const float* __restrict__ W0, const float* __restrict__ W1,
                            const float* __restrict__ W2, const float* __restrict__ W3,
                            const float* __restrict__ tw, const float* __restrict__ alpha,
                            const float* __restrict__ x) {
    int blk = blockIdx.x;
    if (blk < PREP_B0) {
        int i = blk * 256 + threadIdx.x;
        int w = i >> 19;
        int j = i & (NC * KH - 1);
        const float* W = (w == 0) ? W0 : (w == 1) ? W1 : (w == 2) ? W2 : W3;
        float2 v = ((const float2*)W)[j];
        g_Wh[i] = pack2h(v.x, v.y);
    } else if (blk < PREP_B0 + PREP_B1) {
        int i = (blk - PREP_B0) * 256 + threadIdx.x;
        int u = (i & (KH - 1)) * 2;
        int t = (i >> 9) & (NT - 1);
        // 128-block causality: skip tiles never read by the 128-row wkv tiles
        if ((u >> 7) > (t >> 7)) return;
        int h = i >> 19;
        float w0 = 0.f, w1 = 0.f;
        if (u <= t)     w0 = tw[h * NT + 1023 - t + u]     * alpha[h * NT + u];
        if (u + 1 <= t) w1 = tw[h * NT + 1023 - t + u + 1] * alpha[h * NT + u + 1];
        g_WWh[i] = pack2h(w0, w1);
    } else {
        int i = (blk - PREP_B0 - PREP_B1) * 256 + threadIdx.x;
        int kk2 = i & (KH - 1);
        int row = i >> 9;
        int t = row & (NT - 1);
        int c = kk2 * 2;
        float a = 0.f, b = 0.f;
        if (c < NC / 2) {
            if (t != 0) {
                float2 v = *(const float2*)(x + (size_t)(row - 1) * NC + c);
                a = v.x; b = v.y;
            }
        } else {
            float2 v = *(const float2*)(x + (size_t)row * NC + c);
            a = v.x; b = v.y;
        }
        g_Ah[i] = pack2h(a, b);
    }
}

// ---------------- fused: cumsum (segment scans) + kv^T build ------------------
#define CS_BLKS 128

__global__ void cumsum_kvt_kernel() {
    int blk = blockIdx.x;
    if (blk < CS_BLKS) {
        int cp = (blk & 1) * 256 + threadIdx.x;
        int b = (blk >> 1) & 7;
        int s = blk >> 4;
        const uint32_t* src = g_k16 + ((size_t)(b * NT + s * TSEG)) * KH + cp;
        float* dst = g_sumk + ((size_t)(b * NT + s * TSEG)) * NC + cp * 2;
        float a0 = 0.f, a1 = 0.f;
        for (int t0 = 0; t0 < TSEG; t0 += 16) {
            uint32_t buf[16];
#pragma unroll
            for (int j = 0; j < 16; j++) buf[j] = src[(size_t)(t0 + j) * KH];
#pragma unroll
            for (int j = 0; j < 16; j++) {
                float2 kv = unpack2h(buf[j]);
                a0 += kv.x; a1 += kv.y;
                float2 o = {a0, a1};
                *(float2*)&dst[(size_t)(t0 + j) * NC] = o;
            }
        }
        float2 tot = {a0, a1};
        *(float2*)&g_segtot[(b * NSEG + s) * NC + cp * 2] = tot;
    } else {
        __shared__ float skv[64][65];
        int id = blk - CS_BLKS;
        int ut = id & 15;
        int bh = id >> 4;
        int b = bh >> 4, h = bh & 15;
        int tid = threadIdx.x;
        int u0 = ut * 64;
        const __half* kb = (const __half*)g_k16 + ((size_t)(b * NT + u0)) * NC + h * 64;
        const __half* vb = (const __half*)g_v16 + ((size_t)(b * NT + u0)) * NC + h * 64;
#pragma unroll
        for (int rr = 0; rr < 16; rr++) {
            int i = tid + rr * 256;
            int uu = i >> 6, c = i & 63;
            skv[uu][c] = __half2float(kb[(size_t)uu * NC + c]) *
                         __half2float(vb[(size_t)uu * NC + c]);
        }
        __syncthreads();
        uint32_t* oh = g_kvTh + (size_t)bh * 64 * KH + ut * 32;
#pragma unroll
        for (int rr = 0; rr < 8; rr++) {
            int j = tid + rr * 256;
            int c = j >> 5, g = j & 31;
            oh[(size_t)c * KH + g] = pack2h(skv[g * 2][c], skv[g * 2 + 1][c]);
        }
    }
}

// ---------------- wkv + rwkv fused (fp16 MMA, 128x64 tile, 3-stage pipe) -------
#define WR 20
#define WAS (128*WR)            // A region u32 per stage
#define WBS (64*WR)             // B region u32 per stage
#define WSTG (WAS+WBS)

__global__ void __launch_bounds__(256) wkv_mma_kernel(const float* __restrict__ beta) {
    __shared__ uint32_t smw[3 * WSTG];      // 45KB
    int tt = blockIdx.x, bh = blockIdx.y;   // tt in 0..7 (128-row tiles)
    int b = bh >> 4, h = bh & 15;
    int t0 = tt * 128;
    int tid = threadIdx.x;

    // A loads: 128 rows x 16 u32 -> 2 cpa16/thread; B: 64 rows x 16 -> 1 cpa16.
    int arow = tid >> 1, ag = (tid & 1) * 8;
    int brow = tid >> 2, bg = (tid & 3) * 4;
    const uint32_t* pWh = g_WWh + ((size_t)h * NT + t0 + arow) * KH + ag;
    const uint32_t* pKh = g_kvTh + ((size_t)bh * 64 + brow) * KH + bg;
    uint32_t smw_b = (uint32_t)__cvta_generic_to_shared(smw);
    uint32_t sA = smw_b + (arow * WR + ag) * 4;
    uint32_t sB = smw_b + (WAS + brow * WR + bg) * 4;

    int lane = tid & 31, warp = tid >> 5;
    int wm = (warp & 3) * 32, wn = (warp >> 2) * 32;
    int r = lane >> 2, cc = lane & 3;

    int a_base = (wm + (lane & 15)) * WR + (lane >> 4) * 4;
    int b_base = WAS + (wn + ((lane >> 4) << 3) + (lane & 7)) * WR + ((lane >> 3) & 1) * 4;

    float acc[2][4][4];
#pragma unroll
    for (int a = 0; a < 2; a++)
#pragma unroll
        for (int j = 0; j < 4; j++)
#pragma unroll
            for (int q = 0; q < 4; q++) acc[a][j][q] = 0.f;

    int nut = 4 * (tt + 1);     // 32-u tiles, covers u < 128*(tt+1)

#pragma unroll
    for (int s = 0; s < 2; s++) {
        int o = s * 16;
        uint32_t dA = sA + s * WSTG * 4;
        uint32_t dB = sB + s * WSTG * 4;
        cpa16(dA, pWh + o); cpa16(dA + 16, pWh + o + 4);
        cpa16(dB, pKh + o);
        CP_COMMIT();
    }

    for (int ut = 0; ut < nut; ut++) {
        if (ut + 1 < nut) CP_WAIT1(); else CP_WAIT0();
        __syncthreads();
        if (ut + 2 < nut) {
            int slot = (ut + 2) % 3;
            int o = (ut + 2) * 16;
            uint32_t dA = sA + slot * WSTG * 4;
            uint32_t dB = sB + slot * WSTG * 4;
            cpa16(dA, pWh + o); cpa16(dA + 16, pWh + o + 4);
            cpa16(dB, pKh + o);
            CP_COMMIT();
        }

        uint32_t st = (ut % 3) * WSTG;
#pragma unroll
        for (int ks = 0; ks < 2; ks++) {
            uint32_t ah[2][4];
#pragma unroll
            for (int mi = 0; mi < 2; mi++) {
                uint32_t ai = smw_b + (st + a_base + mi * 16 * WR + ks * 8) * 4;
                ldm_x4(ah[mi], ai);
            }
#pragma unroll
            for (int jp = 0; jp < 2; jp++) {
                uint32_t bb[4];
                uint32_t bi = smw_b + (st + b_base + jp * 16 * WR + ks * 8) * 4;
                ldm_x4(bb, bi);
#pragma unroll
                for (int hf = 0; hf < 2; hf++)
#pragma unroll
                    for (int mi = 0; mi < 2; mi++)
                        mma_f16(acc[mi][jp * 2 + hf], ah[mi], bb[hf * 2], bb[hf * 2 + 1]);
            }
        }
    }

    // ---- fused rwkv epilogue (nseg = tt constant across the 128-row tile) ----
    int nseg = tt;
    float so0[4], so1[4];
#pragma unroll
    for (int nj = 0; nj < 4; nj++) {
        int col = h * 64 + wn + nj * 8 + cc * 2;
        float s0 = 0.f, s1 = 0.f;
        for (int sg = 0; sg < nseg; sg++) {
            float2 st = *(const float2*)&g_segtot[(b * NSEG + sg) * NC + col];
            s0 += st.x; s1 += st.y;
        }
        so0[nj] = s0; so1[nj] = s1;
    }
#pragma unroll
    for (int mi = 0; mi < 2; mi++) {
#pragma unroll
        for (int ri = 0; ri < 2; ri++) {
            int t = t0 + wm + mi * 16 + r + ri * 8;
            float be = beta[h * NT + t];
            size_t grow = (size_t)(b * NT + t);
#pragma unroll
            for (int nj = 0; nj < 4; nj++) {
                int col = h * 64 + wn + nj * 8 + cc * 2;
                float2 sk = *(const float2*)&g_sumk[grow * NC + col];
                float2 rv = unpack2h(g_r16[(grow * NC + col) >> 1]);
                float w0 = acc[mi][nj][ri * 2 + 0] * be;
                float w1 = acc[mi][nj][ri * 2 + 1] * be;
                float o0 = (1.f / (1.f + expf(-rv.x))) * w0 / (sk.x + so0[nj]);
                float o1 = (1.f / (1.f + expf(-rv.y))) * w1 / (sk.y + so1[nj]);
                g_Ah[(grow * NC + col) >> 1] = pack2h(o0, o1);
            }
        }
    }
}

// ---------------- fp16 GEMM, 128x64 block, 32x32 warp tile, 3 CTAs/SM ---------
#define RS 20
#define AS (128*RS)
#define BS (64*RS)
#define STG (AS+BS)

template<int MODE>
__global__ void __launch_bounds__(256, 3) gemm_f16_n64(
    const uint32_t* __restrict__ Ah,
    float* __restrict__ Fout,
    const float* __restrict__ b0p, const float* __restrict__ b1p,
    const float* __restrict__ b2p, const float* __restrict__ gamma)
{
    extern __shared__ uint32_t sm[];
    int tid = threadIdx.x;
    int m0 = blockIdx.x * 128;
    int sel, n0;
    const float* bias;
    uint32_t* C16 = nullptr;
    if (MODE == 0) {
        sel = blockIdx.y >> 4;
        n0 = (blockIdx.y & 15) * 64;
        bias = (sel == 0) ? b0p : (sel == 1) ? b1p : b2p;
        C16 = (sel == 0) ? g_k16 : (sel == 1) ? g_v16 : g_r16;
    } else {
        sel = 3;
        n0 = blockIdx.y * 64;
        bias = b0p;
    }
    const uint32_t* Bh = g_Wh + (size_t)sel * NC * KH;

    int arow = tid >> 1, ag = (tid & 1) * 8;
    int brow = tid >> 2, bg = (tid & 3) * 4;
    const uint32_t* pAh = Ah + (size_t)(m0 + arow) * KH + ag;
    const uint32_t* pBh = Bh + (size_t)(n0 + brow) * KH + bg;
    uint32_t smem_b = (uint32_t)__cvta_generic_to_shared(sm);
    uint32_t sA = smem_b + (arow * RS + ag) * 4;
    uint32_t sB = smem_b + (AS + brow * RS + bg) * 4;

    int lane = tid & 31, warp = tid >> 5;
    int wm = (warp & 3) * 32, wn = (warp >> 2) * 32;
    int r = lane >> 2, cc = lane & 3;

    int a_base = (wm + (lane & 15)) * RS + (lane >> 4) * 4;
    int b_base = AS + (wn + ((lane >> 4) << 3) + (lane & 7)) * RS + ((lane >> 3) & 1) * 4;

    float acc[2][4][4];
#pragma unroll
    for (int a = 0; a < 2; a++)
#pragma unroll
        for (int b = 0; b < 4; b++)
#pragma unroll
            for (int q = 0; q < 4; q++) acc[a][b][q] = 0.f;

#pragma unroll
    for (int s = 0; s < 2; s++) {
        int o = s * 16;
        uint32_t dA = sA + s * STG * 4;
        uint32_t dB = sB + s * STG * 4;
        cpa16(dA, pAh + o); cpa16(dA + 16, pAh + o + 4);
        cpa16(dB, pBh + o);
        CP_COMMIT();
    }

    for (int kt = 0; kt < 32; kt++) {
        if (kt + 1 < 32) CP_WAIT1(); else CP_WAIT0();
        __syncthreads();
        if (kt + 2 < 32) {
            int slot = (kt + 2) % 3;
            int o = (kt + 2) * 16;
            uint32_t dA = sA + slot * STG * 4;
            uint32_t dB = sB + slot * STG * 4;
            cpa16(dA, pAh + o); cpa16(dA + 16, pAh + o + 4);
            cpa16(dB, pBh + o);
            CP_COMMIT();
        }

        uint32_t st = (kt % 3) * STG;
#pragma unroll
        for (int ks = 0; ks < 2; ks++) {
            uint32_t ahf[2][4];
#pragma unroll
            for (int mi = 0; mi < 2; mi++) {
                uint32_t ai = smem_b + (st + a_base + mi * 16 * RS + ks * 8) * 4;
                ldm_x4(ahf[mi], ai);
            }
#pragma unroll
            for (int jp = 0; jp < 2; jp++) {
                uint32_t bb[4];
                uint32_t bi = smem_b + (st + b_base + jp * 16 * RS + ks * 8) * 4;
                ldm_x4(bb, bi);
#pragma unroll
                for (int hf = 0; hf < 2; hf++)
#pragma unroll
                    for (int mi = 0; mi < 2; mi++)
                        mma_f16(acc[mi][jp * 2 + hf], ahf[mi], bb[hf * 2], bb[hf * 2 + 1]);
            }
        }
    }

#pragma unroll
    for (int mi = 0; mi < 2; mi++) {
        int mlo = m0 + wm + mi * 16 + r;
        int mhi = mlo + 8;
        float glo = 1.f, ghi = 1.f;
        if (MODE == 1) { glo = gamma[mlo & (NT - 1)]; ghi = gamma[mhi & (NT - 1)]; }
#pragma unroll
        for (int nj = 0; nj < 4; nj++) {
            int col = n0 + wn + nj * 8 + cc * 2;
            float b0 = bias[col], b1 = bias[col + 1];
            float v0 = acc[mi][nj][0] + b0, v1 = acc[mi][nj][1] + b1;
            float v2 = acc[mi][nj][2] + b0, v3 = acc[mi][nj][3] + b1;
            if (MODE == 0) {
                if (sel == 0) {
                    v0 = expf(fminf(fmaxf(v0, -60.f), 30.f));
                    v1 = expf(fminf(fmaxf(v1, -60.f), 30.f));
                    v2 = expf(fminf(fmaxf(v2, -60.f), 30.f));
                    v3 = expf(fminf(fmaxf(v3, -60.f), 30.f));
                }
                C16[((size_t)mlo * NC + col) >> 1] = pack2h(v0, v1);
                C16[((size_t)mhi * NC + col) >> 1] = pack2h(v2, v3);
            } else {
                v0 *= glo; v1 *= glo; v2 *= ghi; v3 *= ghi;
                float2 o01 = {v0, v1}, o23 = {v2, v3};
                *(float2*)&Fout[(size_t)mlo * NC + col] = o01;
                *(float2*)&Fout[(size_t)mhi * NC + col] = o23;
            }
        }
    }
}

// ---------------- host launch -------------------------------------------------
extern "C" void kernel_launch(void* const* d_in, const int* in_sizes, int n_in,
                              void* d_out, int out_size) {
    (void)in_sizes; (void)n_in; (void)out_size;
    const float* x      = (const float*)d_in[0];
    const float* time_w = (const float*)d_in[1];
    const float* alpha  = (const float*)d_in[2];
    const float* beta   = (const float*)d_in[3];
    const float* gamma  = (const float*)d_in[4];
    const float* Wk = (const float*)d_in[5];
    const float* bk = (const float*)d_in[6];
    const float* Wv = (const float*)d_in[7];
    const float* bv = (const float*)d_in[8];
    const float* Wr = (const float*)d_in[9];
    const float* br = (const float*)d_in[10];
    const float* Wo = (const float*)d_in[11];
    const float* bo = (const float*)d_in[12];
    float* out = (float*)d_out;

    uint32_t *Ah;
    cudaGetSymbolAddress((void**)&Ah, g_Ah);

    size_t smem = 3 * STG * 4;   // 46.08KB
    static int attr_set = 0;
    if (!attr_set) {
        cudaFuncSetAttribute(gemm_f16_n64<0>,
                             cudaFuncAttributeMaxDynamicSharedMemorySize, (int)smem);
        cudaFuncSetAttribute(gemm_f16_n64<1>,
                             cudaFuncAttributeMaxDynamicSharedMemorySize, (int)smem);
        attr_set = 1;
    }

    prep_kernel<<<PREP_B0 + PREP_B1 + PREP_B2, 256>>>(Wk, Wv, Wr, Wo, time_w, alpha, x);

    gemm_f16_n64<0><<<dim3(NM / 128, 48), 256, smem>>>(Ah, nullptr, bk, bv, br, nullptr);

    cumsum_kvt_kernel<<<CS_BLKS + NB * NH * (NT / 64), 256>>>();

    wkv_mma_kernel<<<dim3(NT / 128, NB * NH), 256>>>(beta);

    gemm_f16_n64<1><<<dim3(NM / 128, 16), 256, smem>>>(Ah, out, bo, nullptr, nullptr, gamma);
}